// round 13
// baseline (speedup 1.0000x reference)
#include <cuda_runtime.h>
#include <cuda_bf16.h>
#include <cstdint>

// Problem constants
#define Bb 4
#define Ss 2048
#define Nn 2048
#define Dd 1024
#define Hh 16
#define HDd 64
static constexpr float EPS_ = 1e-5f;
static constexpr float QSCALE = 0.125f;   // HD^-0.5

// ---------------------------------------------------------------------------
// Scratch (device globals; no allocation allowed)
// ---------------------------------------------------------------------------
__device__ __nv_bfloat16 g_kh[(size_t)Bb * Nn * HDd];   // layernormed K, bf16 hi
__device__ __nv_bfloat16 g_kl[(size_t)Bb * Nn * HDd];   // layernormed K, bf16 lo
__device__ __nv_bfloat16 g_vh[(size_t)Bb * HDd * Nn];   // V transposed [b][d][n'], hi
__device__ __nv_bfloat16 g_vl[(size_t)Bb * HDd * Nn];   // V transposed, lo
__device__ __nv_bfloat16 g_wh[(size_t)Dd * Dd];         // proj W hi
__device__ __nv_bfloat16 g_wl[(size_t)Dd * Dd];         // proj W lo
__device__ float         g_att[(size_t)Bb * Ss * Dd];   // attention out (B,S,D) fp32
__device__ __nv_bfloat16 g_xh[(size_t)Bb * Ss * Dd];    // layernormed attn out hi
__device__ __nv_bfloat16 g_xl[(size_t)Bb * Ss * Dd];    // layernormed attn out lo

// ---------------------------------------------------------------------------
// helpers
// ---------------------------------------------------------------------------
__device__ __forceinline__ void bsplit(float x, __nv_bfloat16& h, __nv_bfloat16& l) {
    h = __float2bfloat16(x);
    l = __float2bfloat16(x - __bfloat162float(h));
}
__device__ __forceinline__ void mma_bf16(float c[4],
                                         uint32_t a0, uint32_t a1, uint32_t a2, uint32_t a3,
                                         uint32_t b0, uint32_t b1) {
    asm volatile(
        "mma.sync.aligned.m16n8k16.row.col.f32.bf16.bf16.f32 "
        "{%0,%1,%2,%3}, {%4,%5,%6,%7}, {%8,%9}, {%0,%1,%2,%3};"
        : "+f"(c[0]), "+f"(c[1]), "+f"(c[2]), "+f"(c[3])
        : "r"(a0), "r"(a1), "r"(a2), "r"(a3), "r"(b0), "r"(b1));
}
#define MMA3(C, AH0,AH1,AH2,AH3, AL0,AL1,AL2,AL3, BH0,BH1, BL0,BL1) \
    mma_bf16(C, AH0,AH1,AH2,AH3, BH0,BH1);                          \
    mma_bf16(C, AL0,AL1,AL2,AL3, BH0,BH1);                          \
    mma_bf16(C, AH0,AH1,AH2,AH3, BL0,BL1);

__device__ __forceinline__ void cp16(__nv_bfloat16* dst_smem, const __nv_bfloat16* src) {
    uint32_t d = (uint32_t)__cvta_generic_to_shared(dst_smem);
    asm volatile("cp.async.cg.shared.global [%0], [%1], 16;" :: "r"(d), "l"(src) : "memory");
}
#define CP_COMMIT asm volatile("cp.async.commit_group;" ::: "memory")
#define CP_WAIT0  asm volatile("cp.async.wait_group 0;" ::: "memory")

// ---------------------------------------------------------------------------
// Kernel 1: layernorm K rows (B*N rows of 64), warp per row, emit bf16 hi/lo
// ---------------------------------------------------------------------------
__global__ __launch_bounds__(256)
void kln_kernel(const float* __restrict__ xk,
                const float* __restrict__ w,
                const float* __restrict__ bi)
{
    int gw   = (blockIdx.x * blockDim.x + threadIdx.x) >> 5;
    int lane = threadIdx.x & 31;
    if (gw >= Bb * Nn) return;
    const float* row = xk + (size_t)gw * HDd;
    float v0 = row[lane], v1 = row[lane + 32];
    float s = v0 + v1;
#pragma unroll
    for (int o = 16; o; o >>= 1) s += __shfl_xor_sync(0xffffffffu, s, o);
    float mean = s * (1.0f / HDd);
    float d0 = v0 - mean, d1 = v1 - mean;
    float vv = d0 * d0 + d1 * d1;
#pragma unroll
    for (int o = 16; o; o >>= 1) vv += __shfl_xor_sync(0xffffffffu, vv, o);
    float inv = rsqrtf(vv * (1.0f / HDd) + EPS_);
    float o0 = d0 * inv * w[lane]      + bi[lane];
    float o1 = d1 * inv * w[lane + 32] + bi[lane + 32];
    __nv_bfloat16 h, l;
    size_t base = (size_t)gw * HDd;
    bsplit(o0, h, l); g_kh[base + lane]      = h; g_kl[base + lane]      = l;
    bsplit(o1, h, l); g_kh[base + lane + 32] = h; g_kl[base + lane + 32] = l;
}

// ---------------------------------------------------------------------------
// Kernel 1b: transpose + split V:  g_v{h,l}[b][d][n'] = split(xv[b][n'][d])
// ---------------------------------------------------------------------------
__global__ __launch_bounds__(256)
void vprep_kernel(const float* __restrict__ xv)
{
    __shared__ float tile[64][65];
    const int b = blockIdx.y;
    const int t = blockIdx.x;
    const int tid = threadIdx.x;
    const size_t src = (size_t)b * Nn * HDd + (size_t)t * 64 * HDd;
#pragma unroll
    for (int i = 0; i < 4; ++i) {
        int lin = i * 256 + tid;
        int r = lin >> 4, c4 = (lin & 15) * 4;
        float4 v = *(const float4*)(xv + src + (size_t)r * HDd + c4);
        tile[r][c4 + 0] = v.x; tile[r][c4 + 1] = v.y;
        tile[r][c4 + 2] = v.z; tile[r][c4 + 3] = v.w;
    }
    __syncthreads();
    const int d = tid >> 2, g = tid & 3;
    size_t dst = ((size_t)b * HDd + d) * Nn + (size_t)t * 64 + g * 16;
#pragma unroll
    for (int i = 0; i < 16; ++i) {
        __nv_bfloat16 h, l;
        bsplit(tile[g * 16 + i][d], h, l);
        g_vh[dst + i] = h; g_vl[dst + i] = l;
    }
}

// ---------------------------------------------------------------------------
// Kernel 1c: split proj W into bf16 hi/lo
// ---------------------------------------------------------------------------
__global__ __launch_bounds__(256)
void wprep_kernel(const float* __restrict__ W)
{
    size_t g = (size_t)blockIdx.x * 256 + threadIdx.x;   // float4 index
    float4 v = ((const float4*)W)[g];
    __nv_bfloat16 h0,l0,h1,l1,h2,l2,h3,l3;
    bsplit(v.x,h0,l0); bsplit(v.y,h1,l1); bsplit(v.z,h2,l2); bsplit(v.w,h3,l3);
    __nv_bfloat162* ph = (__nv_bfloat162*)(g_wh + g * 4);
    __nv_bfloat162* pl = (__nv_bfloat162*)(g_wl + g * 4);
    ph[0] = __nv_bfloat162(h0, h1); ph[1] = __nv_bfloat162(h2, h3);
    pl[0] = __nv_bfloat162(l0, l1); pl[1] = __nv_bfloat162(l2, l3);
}

// ---------------------------------------------------------------------------
// Kernel 2: bf16 tensor-core flash attention, v3.
//  - P kept in registers (QK C-frag == PV A-frag layout), no smem round-trip
//  - Q-hi A-fragments hoisted to registers (tile-invariant); Q-lo from smem
//  - double-buffered cp.async K/V tile fills, one barrier per tile
// ---------------------------------------------------------------------------
#define BSTR 72              // bf16 elements per smem row
#define USTR 36              // uint32 (bf16x2) per smem row

__global__ __launch_bounds__(256, 2)
void attn_tc_kernel(const float* __restrict__ xq,
                    const float* __restrict__ qw, const float* __restrict__ qb)
{
    extern __shared__ __nv_bfloat16 sbm[];
    __nv_bfloat16* sQh = sbm;                      // 128*72
    __nv_bfloat16* sQl = sQh + 128 * BSTR;
    __nv_bfloat16* stg = sQl + 128 * BSTR;         // 2 stages x 4 arrays x 64*72
    const int KV = 64 * BSTR;                      // 4608 elems per array

    const int b  = blockIdx.z;
    const int h  = blockIdx.y;
    const int s0 = blockIdx.x * 128;
    const int tid = threadIdx.x, wid = tid >> 5, lane = tid & 31;
    const int gr = lane >> 2, tc = lane & 3;
    const int qr = wid * 16;

    const size_t kbase = (size_t)b * Nn * HDd;    // g_k layout [b][n'][d]
    const size_t vbase = (size_t)b * HDd * Nn;    // g_v layout [b][d][n']

    auto fill = [&](int t, int s) {
        __nv_bfloat16* kh = stg + s * 4 * KV;
        __nv_bfloat16* kl = kh + KV;
        __nv_bfloat16* vh = kl + KV;
        __nv_bfloat16* vl = vh + KV;
        const size_t kt = kbase + (size_t)t * 64 * HDd;
        const size_t vt = vbase + (size_t)t * 64;
#pragma unroll
        for (int i = tid; i < 512; i += 256) {
            int row = i >> 3, c = (i & 7) * 8;
            cp16(kh + row * BSTR + c, g_kh + kt + (size_t)row * HDd + c);
            cp16(kl + row * BSTR + c, g_kl + kt + (size_t)row * HDd + c);
            cp16(vh + row * BSTR + c, g_vh + vt + (size_t)row * Nn  + c);
            cp16(vl + row * BSTR + c, g_vl + vt + (size_t)row * Nn  + c);
        }
    };

    // kick off first K/V tile fetch, overlapping Q layernorm
    fill(0, 0);
    CP_COMMIT;

    // --- Q layernorm + scale, bf16-split into smem ---
    {
        const size_t qbase = (size_t)b * (Ss * Dd) + (size_t)h * (Ss * HDd);
#pragma unroll
        for (int it = 0; it < 16; ++it) {
            int r = it * 8 + wid;
            const float* qrow = xq + qbase + (size_t)(s0 + r) * HDd;
            float v0 = qrow[lane], v1 = qrow[lane + 32];
            float s = v0 + v1;
#pragma unroll
            for (int o = 16; o; o >>= 1) s += __shfl_xor_sync(0xffffffffu, s, o);
            float mean = s * (1.0f / HDd);
            float d0 = v0 - mean, d1 = v1 - mean;
            float vv = d0 * d0 + d1 * d1;
#pragma unroll
            for (int o = 16; o; o >>= 1) vv += __shfl_xor_sync(0xffffffffu, vv, o);
            float inv = rsqrtf(vv * (1.0f / HDd) + EPS_);
            float q0 = (d0 * inv * qw[lane]      + qb[lane])      * QSCALE;
            float q1 = (d1 * inv * qw[lane + 32] + qb[lane + 32]) * QSCALE;
            __nv_bfloat16 hh, ll;
            bsplit(q0, hh, ll); sQh[r * BSTR + lane]      = hh; sQl[r * BSTR + lane]      = ll;
            bsplit(q1, hh, ll); sQh[r * BSTR + lane + 32] = hh; sQl[r * BSTR + lane + 32] = ll;
        }
    }
    CP_WAIT0;
    __syncthreads();   // Q staged + stage-0 K/V visible to all

    // --- hoist tile-invariant Q-hi A-fragments into registers ---
    const uint32_t* uQh = (const uint32_t*)sQh;
    const uint32_t* uQl = (const uint32_t*)sQl;
    const int r0u = (qr + gr) * USTR, r1u = (qr + gr + 8) * USTR;
    uint32_t qah[4][4];
#pragma unroll
    for (int c = 0; c < 4; ++c) {
        qah[c][0] = uQh[r0u + c * 8 + tc];
        qah[c][1] = uQh[r1u + c * 8 + tc];
        qah[c][2] = uQh[r0u + c * 8 + 4 + tc];
        qah[c][3] = uQh[r1u + c * 8 + 4 + tc];
    }

    float m0 = -1e30f, m1 = -1e30f, ls0 = 0.0f, ls1 = 0.0f;
    float oa[8][4];
#pragma unroll
    for (int j = 0; j < 8; ++j) { oa[j][0] = oa[j][1] = oa[j][2] = oa[j][3] = 0.0f; }

    for (int t = 0; t < Nn / 64; ++t) {
        const int cur = t & 1;
        if (t + 1 < Nn / 64) { fill(t + 1, cur ^ 1); CP_COMMIT; }

        const uint32_t* uKh = (const uint32_t*)(stg + cur * 4 * KV);
        const uint32_t* uKl = uKh + KV / 2;
        const uint32_t* uVh = uKl + KV / 2;
        const uint32_t* uVl = uVh + KV / 2;

        // ---- S = Q K^T : 4 k16-chunks, 3-term bf16, A from regs + Q-lo smem ----
        float sc[8][4];
#pragma unroll
        for (int j = 0; j < 8; ++j) { sc[j][0] = sc[j][1] = sc[j][2] = sc[j][3] = 0.0f; }
#pragma unroll
        for (int c = 0; c < 4; ++c) {
            uint32_t ql0 = uQl[r0u + c * 8 + tc],     ql1 = uQl[r1u + c * 8 + tc];
            uint32_t ql2 = uQl[r0u + c * 8 + 4 + tc], ql3 = uQl[r1u + c * 8 + 4 + tc];
#pragma unroll
            for (int j = 0; j < 8; ++j) {
                int bi = (j * 8 + gr) * USTR + c * 8 + tc;
                uint32_t bh0 = uKh[bi], bh1 = uKh[bi + 4];
                uint32_t bl0 = uKl[bi], bl1 = uKl[bi + 4];
                MMA3(sc[j], qah[c][0],qah[c][1],qah[c][2],qah[c][3],
                            ql0,ql1,ql2,ql3, bh0,bh1, bl0,bl1);
            }
        }

        // ---- online softmax; P packed straight into PV A-fragments ----
        float tm0 = -1e30f, tm1 = -1e30f;
#pragma unroll
        for (int j = 0; j < 8; ++j) {
            tm0 = fmaxf(tm0, fmaxf(sc[j][0], sc[j][1]));
            tm1 = fmaxf(tm1, fmaxf(sc[j][2], sc[j][3]));
        }
        tm0 = fmaxf(tm0, __shfl_xor_sync(0xffffffffu, tm0, 1));
        tm0 = fmaxf(tm0, __shfl_xor_sync(0xffffffffu, tm0, 2));
        tm1 = fmaxf(tm1, __shfl_xor_sync(0xffffffffu, tm1, 1));
        tm1 = fmaxf(tm1, __shfl_xor_sync(0xffffffffu, tm1, 2));
        float mn0 = fmaxf(m0, tm0), mn1 = fmaxf(m1, tm1);
        float cr0 = __expf(m0 - mn0), cr1 = __expf(m1 - mn1);
        m0 = mn0; m1 = mn1;
        float rs0 = 0.0f, rs1 = 0.0f;
        uint32_t pah[4][4], pal[4][4];
#pragma unroll
        for (int j = 0; j < 8; ++j) {
            float p00 = __expf(sc[j][0] - mn0), p01 = __expf(sc[j][1] - mn0);
            float p10 = __expf(sc[j][2] - mn1), p11 = __expf(sc[j][3] - mn1);
            rs0 += p00 + p01; rs1 += p10 + p11;
            oa[j][0] *= cr0; oa[j][1] *= cr0; oa[j][2] *= cr1; oa[j][3] *= cr1;
            __nv_bfloat162 hp0 = __floats2bfloat162_rn(p00, p01);
            float2 hf0 = __bfloat1622float2(hp0);
            __nv_bfloat162 lp0 = __floats2bfloat162_rn(p00 - hf0.x, p01 - hf0.y);
            __nv_bfloat162 hp1 = __floats2bfloat162_rn(p10, p11);
            float2 hf1 = __bfloat1622float2(hp1);
            __nv_bfloat162 lp1 = __floats2bfloat162_rn(p10 - hf1.x, p11 - hf1.y);
            int c = j >> 1, o = (j & 1) * 2;
            pah[c][o] = *(uint32_t*)&hp0; pah[c][o + 1] = *(uint32_t*)&hp1;
            pal[c][o] = *(uint32_t*)&lp0; pal[c][o + 1] = *(uint32_t*)&lp1;
        }
        rs0 += __shfl_xor_sync(0xffffffffu, rs0, 1);
        rs0 += __shfl_xor_sync(0xffffffffu, rs0, 2);
        rs1 += __shfl_xor_sync(0xffffffffu, rs1, 1);
        rs1 += __shfl_xor_sync(0xffffffffu, rs1, 2);
        ls0 = ls0 * cr0 + rs0;
        ls1 = ls1 * cr1 + rs1;

        // ---- O += P V : A = P regs, B = V^T rows from smem ----
#pragma unroll
        for (int c = 0; c < 4; ++c) {
#pragma unroll
            for (int j = 0; j < 8; ++j) {
                int bi = (j * 8 + gr) * USTR + c * 8 + tc;
                uint32_t bh0 = uVh[bi], bh1 = uVh[bi + 4];
                uint32_t bl0 = uVl[bi], bl1 = uVl[bi + 4];
                MMA3(oa[j], pah[c][0],pah[c][1],pah[c][2],pah[c][3],
                            pal[c][0],pal[c][1],pal[c][2],pal[c][3],
                            bh0,bh1, bl0,bl1);
            }
        }

        if (t + 1 < Nn / 64) CP_WAIT0;
        __syncthreads();   // all warps done reading buf[cur]; next fill may reuse it
    }

    // ---- epilogue: normalize, scatter to (B, S, H*HD) ----
    float i0 = 1.0f / ls0, i1 = 1.0f / ls1;
    size_t r0 = (size_t)b * (Ss * Dd) + (size_t)(s0 + qr + gr) * Dd + h * HDd;
    size_t r1 = r0 + (size_t)8 * Dd;
#pragma unroll
    for (int j = 0; j < 8; ++j) {
        *(float2*)(g_att + r0 + j * 8 + 2 * tc) = make_float2(oa[j][0] * i0, oa[j][1] * i0);
        *(float2*)(g_att + r1 + j * 8 + 2 * tc) = make_float2(oa[j][2] * i1, oa[j][3] * i1);
    }
}

// ---------------------------------------------------------------------------
// Kernel 3: layernorm over D=1024, emits bf16 hi/lo for the proj GEMM.
// Guarded cross-warp shuffle uses an 8-lane mask (full-mask here deadlocks).
// ---------------------------------------------------------------------------
__global__ __launch_bounds__(256)
void lnd_kernel(const float* __restrict__ w, const float* __restrict__ bi)
{
    __shared__ float sb2[8];
    int row = blockIdx.x;
    int tid = threadIdx.x;
    int wid = tid >> 5, lane = tid & 31;

    float4 v = *(const float4*)(g_att + (size_t)row * Dd + tid * 4);

    float s = v.x + v.y + v.z + v.w;
#pragma unroll
    for (int o = 16; o; o >>= 1) s += __shfl_xor_sync(0xffffffffu, s, o);
    if (lane == 0) sb2[wid] = s;
    __syncthreads();
    if (tid < 8) {
        float t = sb2[tid];
#pragma unroll
        for (int o = 4; o; o >>= 1) t += __shfl_xor_sync(0xFFu, t, o);
        if (tid == 0) sb2[0] = t;
    }
    __syncthreads();
    float mean = sb2[0] * (1.0f / Dd);
    __syncthreads();

    float dx = v.x - mean, dy = v.y - mean, dz = v.z - mean, dw = v.w - mean;
    float vv = dx * dx + dy * dy + dz * dz + dw * dw;
#pragma unroll
    for (int o = 16; o; o >>= 1) vv += __shfl_xor_sync(0xffffffffu, vv, o);
    if (lane == 0) sb2[wid] = vv;
    __syncthreads();
    if (tid < 8) {
        float t = sb2[tid];
#pragma unroll
        for (int o = 4; o; o >>= 1) t += __shfl_xor_sync(0xFFu, t, o);
        if (tid == 0) sb2[0] = t;
    }
    __syncthreads();
    float inv = rsqrtf(sb2[0] * (1.0f / Dd) + EPS_);

    float4 w4 = *(const float4*)(w  + tid * 4);
    float4 b4 = *(const float4*)(bi + tid * 4);
    float rx = dx * inv * w4.x + b4.x;
    float ry = dy * inv * w4.y + b4.y;
    float rz = dz * inv * w4.z + b4.z;
    float rw = dw * inv * w4.w + b4.w;

    __nv_bfloat162 h01 = __floats2bfloat162_rn(rx, ry);
    __nv_bfloat162 h23 = __floats2bfloat162_rn(rz, rw);
    float2 f01 = __bfloat1622float2(h01), f23 = __bfloat1622float2(h23);
    __nv_bfloat162 l01 = __floats2bfloat162_rn(rx - f01.x, ry - f01.y);
    __nv_bfloat162 l23 = __floats2bfloat162_rn(rz - f23.x, rw - f23.y);
    __nv_bfloat162* ph = (__nv_bfloat162*)(g_xh + (size_t)row * Dd + tid * 4);
    __nv_bfloat162* pl = (__nv_bfloat162*)(g_xl + (size_t)row * Dd + tid * 4);
    ph[0] = h01; ph[1] = h23;
    pl[0] = l01; pl[1] = l23;
}

// ---------------------------------------------------------------------------
// Kernel 4: out = xln @ proj_w^T via bf16 3-term MMAs.
// Block = 128(m) x 64(n), BK=64, double-buffered cp.async tile fills.
// ---------------------------------------------------------------------------
__global__ __launch_bounds__(256, 2)
void proj_tc_kernel(float* __restrict__ out)
{
    extern __shared__ __nv_bfloat16 sbm[];
    const int XSZ = 128 * BSTR;       // 9216 elems
    const int WSZ = 64 * BSTR;        // 4608 elems
    const int STG = 2 * XSZ + 2 * WSZ;

    const int m0 = blockIdx.y * 128;
    const int n0 = blockIdx.x * 64;
    const int tid = threadIdx.x, wid = tid >> 5, lane = tid & 31;
    const int gr = lane >> 2, tc = lane & 3;
    const int qr = wid * 16;

    auto fill = [&](int kt, int s) {
        __nv_bfloat16* xh = sbm + s * STG;
        __nv_bfloat16* xl = xh + XSZ;
        __nv_bfloat16* wh = xl + XSZ;
        __nv_bfloat16* wl = wh + WSZ;
#pragma unroll
        for (int i = tid; i < 1024; i += 256) {
            int row = i >> 3, c = (i & 7) * 8;
            cp16(xh + row * BSTR + c, g_xh + (size_t)(m0 + row) * Dd + kt + c);
            cp16(xl + row * BSTR + c, g_xl + (size_t)(m0 + row) * Dd + kt + c);
        }
#pragma unroll
        for (int i = tid; i < 512; i += 256) {
            int row = i >> 3, c = (i & 7) * 8;
            cp16(wh + row * BSTR + c, g_wh + (size_t)(n0 + row) * Dd + kt + c);
            cp16(wl + row * BSTR + c, g_wl + (size_t)(n0 + row) * Dd + kt + c);
        }
    };

    fill(0, 0);
    CP_COMMIT;

    float oa[8][4];
#pragma unroll
    for (int j = 0; j < 8; ++j) { oa[j][0] = oa[j][1] = oa[j][2] = oa[j][3] = 0.0f; }

    CP_WAIT0;
    __syncthreads();

    const int r0u = (qr + gr) * USTR, r1u = (qr + gr + 8) * USTR;

    for (int ki = 0; ki < Dd / 64; ++ki) {
        const int cur = ki & 1;
        if (ki + 1 < Dd / 64) { fill((ki + 1) * 64, cur ^ 1); CP_COMMIT; }

        const uint32_t* uXh = (const uint32_t*)(sbm + cur * STG);
        const uint32_t* uXl = uXh + XSZ / 2;
        const uint32_t* uWh = uXl + XSZ / 2;
        const uint32_t* uWl = uWh + WSZ / 2;

#pragma unroll
        for (int c = 0; c < 4; ++c) {
            uint32_t ah0 = uXh[r0u + c * 8 + tc],     ah1 = uXh[r1u + c * 8 + tc];
            uint32_t ah2 = uXh[r0u + c * 8 + 4 + tc], ah3 = uXh[r1u + c * 8 + 4 + tc];
            uint32_t al0 = uXl[r0u + c * 8 + tc],     al1 = uXl[r1u + c * 8 + tc];
            uint32_t al2 = uXl[r0u + c * 8 + 4 + tc], al3 = uXl[r1u + c * 8 + 4 + tc];
#pragma unroll
            for (int j = 0; j < 8; ++j) {
                int bi = (j * 8 + gr) * USTR + c * 8 + tc;
                uint32_t bh0 = uWh[bi], bh1 = uWh[bi + 4];
                uint32_t bl0 = uWl[bi], bl1 = uWl[bi + 4];
                MMA3(oa[j], ah0,ah1,ah2,ah3, al0,al1,al2,al3, bh0,bh1, bl0,bl1);
            }
        }

        if (ki + 1 < Dd / 64) CP_WAIT0;
        __syncthreads();
    }

    size_t r0 = (size_t)(m0 + qr + gr) * Dd + n0;
    size_t r1 = r0 + (size_t)8 * Dd;
#pragma unroll
    for (int j = 0; j < 8; ++j) {
        *(float2*)(out + r0 + j * 8 + 2 * tc) = make_float2(oa[j][0], oa[j][1]);
        *(float2*)(out + r1 + j * 8 + 2 * tc) = make_float2(oa[j][2], oa[j][3]);
    }
}

// ---------------------------------------------------------------------------
// Launch
// Inputs: 0 x_q, 1 x_k, 2 x_v, 3 qn_w, 4 qn_b, 5 kn_w, 6 kn_b, 7 n_w, 8 n_b, 9 proj_w
// ---------------------------------------------------------------------------
extern "C" void kernel_launch(void* const* d_in, const int* in_sizes, int n_in,
                              void* d_out, int out_size)
{
    const float* xq  = (const float*)d_in[0];
    const float* xk  = (const float*)d_in[1];
    const float* xv  = (const float*)d_in[2];
    const float* qnw = (const float*)d_in[3];
    const float* qnb = (const float*)d_in[4];
    const float* knw = (const float*)d_in[5];
    const float* knb = (const float*)d_in[6];
    const float* nw  = (const float*)d_in[7];
    const float* nb  = (const float*)d_in[8];
    const float* pw  = (const float*)d_in[9];
    float* out = (float*)d_out;

    const int ATTN_SMEM = (2 * 128 * BSTR + 2 * 4 * 64 * BSTR) * 2;   // 110592 B
    const int PROJ_SMEM = 2 * (2 * 128 * BSTR + 2 * 64 * BSTR) * 2;   // 110592 B
    cudaFuncSetAttribute(attn_tc_kernel, cudaFuncAttributeMaxDynamicSharedMemorySize, ATTN_SMEM);
    cudaFuncSetAttribute(proj_tc_kernel, cudaFuncAttributeMaxDynamicSharedMemorySize, PROJ_SMEM);

    // 1) prep: K layernorm+split, V transpose+split, W split
    kln_kernel<<<(Bb * Nn) / 8, 256>>>(xk, knw, knb);
    dim3 vgrid(Nn / 64, Bb);
    vprep_kernel<<<vgrid, 256>>>(xv);
    wprep_kernel<<<(Dd * Dd / 4) / 256, 256>>>(pw);

    // 2) bf16 tensor-core flash attention : (S/128, H, B)
    dim3 agrid(Ss / 128, Hh, Bb);
    attn_tc_kernel<<<agrid, 256, ATTN_SMEM>>>(xq, qnw, qnb);

    // 3) layernorm over D (emits bf16 hi/lo)
    lnd_kernel<<<Bb * Ss, 256>>>(nw, nb);

    // 4) projection GEMM : (N/64, M/128)
    dim3 pgrid(Dd / 64, (Bb * Ss) / 128);
    proj_tc_kernel<<<pgrid, 256, PROJ_SMEM>>>(out);
}

// round 14
// speedup vs baseline: 1.5022x; 1.5022x over previous
#include <cuda_runtime.h>
#include <cuda_bf16.h>
#include <cstdint>

// Problem constants
#define Bb 4
#define Ss 2048
#define Nn 2048
#define Dd 1024
#define Hh 16
#define HDd 64
static constexpr float EPS_ = 1e-5f;
static constexpr float QSCALE = 0.125f;   // HD^-0.5

// ---------------------------------------------------------------------------
// Scratch (device globals; no allocation allowed)
// ---------------------------------------------------------------------------
__device__ __nv_bfloat16 g_kh[(size_t)Bb * Nn * HDd];   // layernormed K, bf16 hi
__device__ __nv_bfloat16 g_kl[(size_t)Bb * Nn * HDd];   // layernormed K, bf16 lo
__device__ __nv_bfloat16 g_vh[(size_t)Bb * HDd * Nn];   // V transposed [b][d][n'], hi
__device__ __nv_bfloat16 g_vl[(size_t)Bb * HDd * Nn];   // V transposed, lo
__device__ __nv_bfloat16 g_wh[(size_t)Dd * Dd];         // proj W hi
__device__ __nv_bfloat16 g_wl[(size_t)Dd * Dd];         // proj W lo
__device__ float         g_att[(size_t)Bb * Ss * Dd];   // attention out (B,S,D) fp32
__device__ __nv_bfloat16 g_xh[(size_t)Bb * Ss * Dd];    // layernormed attn out hi
__device__ __nv_bfloat16 g_xl[(size_t)Bb * Ss * Dd];    // layernormed attn out lo

// ---------------------------------------------------------------------------
// helpers
// ---------------------------------------------------------------------------
__device__ __forceinline__ void bsplit(float x, __nv_bfloat16& h, __nv_bfloat16& l) {
    h = __float2bfloat16(x);
    l = __float2bfloat16(x - __bfloat162float(h));
}
__device__ __forceinline__ void mma_bf16(float c[4],
                                         uint32_t a0, uint32_t a1, uint32_t a2, uint32_t a3,
                                         uint32_t b0, uint32_t b1) {
    asm volatile(
        "mma.sync.aligned.m16n8k16.row.col.f32.bf16.bf16.f32 "
        "{%0,%1,%2,%3}, {%4,%5,%6,%7}, {%8,%9}, {%0,%1,%2,%3};"
        : "+f"(c[0]), "+f"(c[1]), "+f"(c[2]), "+f"(c[3])
        : "r"(a0), "r"(a1), "r"(a2), "r"(a3), "r"(b0), "r"(b1));
}
#define MMA3(C, AH0,AH1,AH2,AH3, AL0,AL1,AL2,AL3, BH0,BH1, BL0,BL1) \
    mma_bf16(C, AH0,AH1,AH2,AH3, BH0,BH1);                          \
    mma_bf16(C, AL0,AL1,AL2,AL3, BH0,BH1);                          \
    mma_bf16(C, AH0,AH1,AH2,AH3, BL0,BL1);

__device__ __forceinline__ void cp16(__nv_bfloat16* dst_smem, const __nv_bfloat16* src) {
    uint32_t d = (uint32_t)__cvta_generic_to_shared(dst_smem);
    asm volatile("cp.async.cg.shared.global [%0], [%1], 16;" :: "r"(d), "l"(src) : "memory");
}
#define CP_COMMIT asm volatile("cp.async.commit_group;" ::: "memory")
#define CP_WAIT0  asm volatile("cp.async.wait_group 0;" ::: "memory")

// ---------------------------------------------------------------------------
// Kernel 1: layernorm K rows (B*N rows of 64), warp per row, emit bf16 hi/lo
// ---------------------------------------------------------------------------
__global__ __launch_bounds__(256)
void kln_kernel(const float* __restrict__ xk,
                const float* __restrict__ w,
                const float* __restrict__ bi)
{
    int gw   = (blockIdx.x * blockDim.x + threadIdx.x) >> 5;
    int lane = threadIdx.x & 31;
    if (gw >= Bb * Nn) return;
    const float* row = xk + (size_t)gw * HDd;
    float v0 = row[lane], v1 = row[lane + 32];
    float s = v0 + v1;
#pragma unroll
    for (int o = 16; o; o >>= 1) s += __shfl_xor_sync(0xffffffffu, s, o);
    float mean = s * (1.0f / HDd);
    float d0 = v0 - mean, d1 = v1 - mean;
    float vv = d0 * d0 + d1 * d1;
#pragma unroll
    for (int o = 16; o; o >>= 1) vv += __shfl_xor_sync(0xffffffffu, vv, o);
    float inv = rsqrtf(vv * (1.0f / HDd) + EPS_);
    float o0 = d0 * inv * w[lane]      + bi[lane];
    float o1 = d1 * inv * w[lane + 32] + bi[lane + 32];
    __nv_bfloat16 h, l;
    size_t base = (size_t)gw * HDd;
    bsplit(o0, h, l); g_kh[base + lane]      = h; g_kl[base + lane]      = l;
    bsplit(o1, h, l); g_kh[base + lane + 32] = h; g_kl[base + lane + 32] = l;
}

// ---------------------------------------------------------------------------
// Kernel 1b: transpose + split V:  g_v{h,l}[b][d][n'] = split(xv[b][n'][d])
// ---------------------------------------------------------------------------
__global__ __launch_bounds__(256)
void vprep_kernel(const float* __restrict__ xv)
{
    __shared__ float tile[64][65];
    const int b = blockIdx.y;
    const int t = blockIdx.x;
    const int tid = threadIdx.x;
    const size_t src = (size_t)b * Nn * HDd + (size_t)t * 64 * HDd;
#pragma unroll
    for (int i = 0; i < 4; ++i) {
        int lin = i * 256 + tid;
        int r = lin >> 4, c4 = (lin & 15) * 4;
        float4 v = *(const float4*)(xv + src + (size_t)r * HDd + c4);
        tile[r][c4 + 0] = v.x; tile[r][c4 + 1] = v.y;
        tile[r][c4 + 2] = v.z; tile[r][c4 + 3] = v.w;
    }
    __syncthreads();
    const int d = tid >> 2, g = tid & 3;
    size_t dst = ((size_t)b * HDd + d) * Nn + (size_t)t * 64 + g * 16;
#pragma unroll
    for (int i = 0; i < 16; ++i) {
        __nv_bfloat16 h, l;
        bsplit(tile[g * 16 + i][d], h, l);
        g_vh[dst + i] = h; g_vl[dst + i] = l;
    }
}

// ---------------------------------------------------------------------------
// Kernel 1c: split proj W into bf16 hi/lo
// ---------------------------------------------------------------------------
__global__ __launch_bounds__(256)
void wprep_kernel(const float* __restrict__ W)
{
    size_t g = (size_t)blockIdx.x * 256 + threadIdx.x;   // float4 index
    float4 v = ((const float4*)W)[g];
    __nv_bfloat16 h0,l0,h1,l1,h2,l2,h3,l3;
    bsplit(v.x,h0,l0); bsplit(v.y,h1,l1); bsplit(v.z,h2,l2); bsplit(v.w,h3,l3);
    __nv_bfloat162* ph = (__nv_bfloat162*)(g_wh + g * 4);
    __nv_bfloat162* pl = (__nv_bfloat162*)(g_wl + g * 4);
    ph[0] = __nv_bfloat162(h0, h1); ph[1] = __nv_bfloat162(h2, h3);
    pl[0] = __nv_bfloat162(l0, l1); pl[1] = __nv_bfloat162(l2, l3);
}

// ---------------------------------------------------------------------------
// Kernel 2: bf16 tensor-core flash attention, v4.
//  - P lives in registers only per-chunk (8 regs): softmax and PV interleaved
//    chunk-by-chunk, so sc dies as P is born -> no spills under the 128-reg cap
//  - Q hi AND lo read from smem each tile (no hoist; keeps pressure low)
//  - double-buffered cp.async K/V tile fills, one barrier per tile
// ---------------------------------------------------------------------------
#define BSTR 72              // bf16 elements per smem row
#define USTR 36              // uint32 (bf16x2) per smem row

__global__ __launch_bounds__(256, 2)
void attn_tc_kernel(const float* __restrict__ xq,
                    const float* __restrict__ qw, const float* __restrict__ qb)
{
    extern __shared__ __nv_bfloat16 sbm[];
    __nv_bfloat16* sQh = sbm;                      // 128*72
    __nv_bfloat16* sQl = sQh + 128 * BSTR;
    __nv_bfloat16* stg = sQl + 128 * BSTR;         // 2 stages x 4 arrays x 64*72
    const int KV = 64 * BSTR;                      // 4608 elems per array

    const int b  = blockIdx.z;
    const int h  = blockIdx.y;
    const int s0 = blockIdx.x * 128;
    const int tid = threadIdx.x, wid = tid >> 5, lane = tid & 31;
    const int gr = lane >> 2, tc = lane & 3;
    const int qr = wid * 16;

    const size_t kbase = (size_t)b * Nn * HDd;    // g_k layout [b][n'][d]
    const size_t vbase = (size_t)b * HDd * Nn;    // g_v layout [b][d][n']

    auto fill = [&](int t, int s) {
        __nv_bfloat16* kh = stg + s * 4 * KV;
        __nv_bfloat16* kl = kh + KV;
        __nv_bfloat16* vh = kl + KV;
        __nv_bfloat16* vl = vh + KV;
        const size_t kt = kbase + (size_t)t * 64 * HDd;
        const size_t vt = vbase + (size_t)t * 64;
#pragma unroll
        for (int i = tid; i < 512; i += 256) {
            int row = i >> 3, c = (i & 7) * 8;
            cp16(kh + row * BSTR + c, g_kh + kt + (size_t)row * HDd + c);
            cp16(kl + row * BSTR + c, g_kl + kt + (size_t)row * HDd + c);
            cp16(vh + row * BSTR + c, g_vh + vt + (size_t)row * Nn  + c);
            cp16(vl + row * BSTR + c, g_vl + vt + (size_t)row * Nn  + c);
        }
    };

    // kick off first K/V tile fetch, overlapping Q layernorm
    fill(0, 0);
    CP_COMMIT;

    // --- Q layernorm + scale, bf16-split into smem ---
    {
        const size_t qbase = (size_t)b * (Ss * Dd) + (size_t)h * (Ss * HDd);
#pragma unroll
        for (int it = 0; it < 16; ++it) {
            int r = it * 8 + wid;
            const float* qrow = xq + qbase + (size_t)(s0 + r) * HDd;
            float v0 = qrow[lane], v1 = qrow[lane + 32];
            float s = v0 + v1;
#pragma unroll
            for (int o = 16; o; o >>= 1) s += __shfl_xor_sync(0xffffffffu, s, o);
            float mean = s * (1.0f / HDd);
            float d0 = v0 - mean, d1 = v1 - mean;
            float vv = d0 * d0 + d1 * d1;
#pragma unroll
            for (int o = 16; o; o >>= 1) vv += __shfl_xor_sync(0xffffffffu, vv, o);
            float inv = rsqrtf(vv * (1.0f / HDd) + EPS_);
            float q0 = (d0 * inv * qw[lane]      + qb[lane])      * QSCALE;
            float q1 = (d1 * inv * qw[lane + 32] + qb[lane + 32]) * QSCALE;
            __nv_bfloat16 hh, ll;
            bsplit(q0, hh, ll); sQh[r * BSTR + lane]      = hh; sQl[r * BSTR + lane]      = ll;
            bsplit(q1, hh, ll); sQh[r * BSTR + lane + 32] = hh; sQl[r * BSTR + lane + 32] = ll;
        }
    }
    CP_WAIT0;
    __syncthreads();   // Q staged + stage-0 K/V visible to all

    const uint32_t* uQh = (const uint32_t*)sQh;
    const uint32_t* uQl = (const uint32_t*)sQl;
    const int r0u = (qr + gr) * USTR, r1u = (qr + gr + 8) * USTR;

    float m0 = -1e30f, m1 = -1e30f, ls0 = 0.0f, ls1 = 0.0f;
    float oa[8][4];
#pragma unroll
    for (int j = 0; j < 8; ++j) { oa[j][0] = oa[j][1] = oa[j][2] = oa[j][3] = 0.0f; }

    for (int t = 0; t < Nn / 64; ++t) {
        const int cur = t & 1;
        if (t + 1 < Nn / 64) { fill(t + 1, cur ^ 1); CP_COMMIT; }

        const uint32_t* uKh = (const uint32_t*)(stg + cur * 4 * KV);
        const uint32_t* uKl = uKh + KV / 2;
        const uint32_t* uVh = uKl + KV / 2;
        const uint32_t* uVl = uVh + KV / 2;

        // ---- S = Q K^T : 4 k16-chunks, 3-term bf16, A frags from smem ----
        float sc[8][4];
#pragma unroll
        for (int j = 0; j < 8; ++j) { sc[j][0] = sc[j][1] = sc[j][2] = sc[j][3] = 0.0f; }
#pragma unroll
        for (int c = 0; c < 4; ++c) {
            uint32_t qh0 = uQh[r0u + c * 8 + tc],     qh1 = uQh[r1u + c * 8 + tc];
            uint32_t qh2 = uQh[r0u + c * 8 + 4 + tc], qh3 = uQh[r1u + c * 8 + 4 + tc];
            uint32_t ql0 = uQl[r0u + c * 8 + tc],     ql1 = uQl[r1u + c * 8 + tc];
            uint32_t ql2 = uQl[r0u + c * 8 + 4 + tc], ql3 = uQl[r1u + c * 8 + 4 + tc];
#pragma unroll
            for (int j = 0; j < 8; ++j) {
                int bi = (j * 8 + gr) * USTR + c * 8 + tc;
                uint32_t bh0 = uKh[bi], bh1 = uKh[bi + 4];
                uint32_t bl0 = uKl[bi], bl1 = uKl[bi + 4];
                MMA3(sc[j], qh0,qh1,qh2,qh3, ql0,ql1,ql2,ql3, bh0,bh1, bl0,bl1);
            }
        }

        // ---- online softmax: row max, correction, oa rescale ----
        float tm0 = -1e30f, tm1 = -1e30f;
#pragma unroll
        for (int j = 0; j < 8; ++j) {
            tm0 = fmaxf(tm0, fmaxf(sc[j][0], sc[j][1]));
            tm1 = fmaxf(tm1, fmaxf(sc[j][2], sc[j][3]));
        }
        tm0 = fmaxf(tm0, __shfl_xor_sync(0xffffffffu, tm0, 1));
        tm0 = fmaxf(tm0, __shfl_xor_sync(0xffffffffu, tm0, 2));
        tm1 = fmaxf(tm1, __shfl_xor_sync(0xffffffffu, tm1, 1));
        tm1 = fmaxf(tm1, __shfl_xor_sync(0xffffffffu, tm1, 2));
        float mn0 = fmaxf(m0, tm0), mn1 = fmaxf(m1, tm1);
        float cr0 = __expf(m0 - mn0), cr1 = __expf(m1 - mn1);
        m0 = mn0; m1 = mn1;
#pragma unroll
        for (int j = 0; j < 8; ++j) {
            oa[j][0] *= cr0; oa[j][1] *= cr0; oa[j][2] *= cr1; oa[j][3] *= cr1;
        }

        // ---- per-chunk: exp+pack P (8 regs live), then PV MMAs for chunk ----
        float rs0 = 0.0f, rs1 = 0.0f;
#pragma unroll
        for (int c = 0; c < 4; ++c) {
            uint32_t pah[4], pal[4];
#pragma unroll
            for (int jj = 0; jj < 2; ++jj) {
                int j = 2 * c + jj;
                float p00 = __expf(sc[j][0] - mn0), p01 = __expf(sc[j][1] - mn0);
                float p10 = __expf(sc[j][2] - mn1), p11 = __expf(sc[j][3] - mn1);
                rs0 += p00 + p01; rs1 += p10 + p11;
                __nv_bfloat162 hp0 = __floats2bfloat162_rn(p00, p01);
                float2 hf0 = __bfloat1622float2(hp0);
                __nv_bfloat162 lp0 = __floats2bfloat162_rn(p00 - hf0.x, p01 - hf0.y);
                __nv_bfloat162 hp1 = __floats2bfloat162_rn(p10, p11);
                float2 hf1 = __bfloat1622float2(hp1);
                __nv_bfloat162 lp1 = __floats2bfloat162_rn(p10 - hf1.x, p11 - hf1.y);
                pah[jj * 2] = *(uint32_t*)&hp0; pah[jj * 2 + 1] = *(uint32_t*)&hp1;
                pal[jj * 2] = *(uint32_t*)&lp0; pal[jj * 2 + 1] = *(uint32_t*)&lp1;
            }
#pragma unroll
            for (int j = 0; j < 8; ++j) {
                int bi = (j * 8 + gr) * USTR + c * 8 + tc;
                uint32_t bh0 = uVh[bi], bh1 = uVh[bi + 4];
                uint32_t bl0 = uVl[bi], bl1 = uVl[bi + 4];
                MMA3(oa[j], pah[0],pah[1],pah[2],pah[3],
                            pal[0],pal[1],pal[2],pal[3], bh0,bh1, bl0,bl1);
            }
        }
        rs0 += __shfl_xor_sync(0xffffffffu, rs0, 1);
        rs0 += __shfl_xor_sync(0xffffffffu, rs0, 2);
        rs1 += __shfl_xor_sync(0xffffffffu, rs1, 1);
        rs1 += __shfl_xor_sync(0xffffffffu, rs1, 2);
        ls0 = ls0 * cr0 + rs0;
        ls1 = ls1 * cr1 + rs1;

        if (t + 1 < Nn / 64) CP_WAIT0;
        __syncthreads();   // all warps done reading buf[cur]; next fill may reuse it
    }

    // ---- epilogue: normalize, scatter to (B, S, H*HD) ----
    float i0 = 1.0f / ls0, i1 = 1.0f / ls1;
    size_t r0 = (size_t)b * (Ss * Dd) + (size_t)(s0 + qr + gr) * Dd + h * HDd;
    size_t r1 = r0 + (size_t)8 * Dd;
#pragma unroll
    for (int j = 0; j < 8; ++j) {
        *(float2*)(g_att + r0 + j * 8 + 2 * tc) = make_float2(oa[j][0] * i0, oa[j][1] * i0);
        *(float2*)(g_att + r1 + j * 8 + 2 * tc) = make_float2(oa[j][2] * i1, oa[j][3] * i1);
    }
}

// ---------------------------------------------------------------------------
// Kernel 3: layernorm over D=1024, emits bf16 hi/lo for the proj GEMM.
// Guarded cross-warp shuffle uses an 8-lane mask (full-mask here deadlocks).
// ---------------------------------------------------------------------------
__global__ __launch_bounds__(256)
void lnd_kernel(const float* __restrict__ w, const float* __restrict__ bi)
{
    __shared__ float sb2[8];
    int row = blockIdx.x;
    int tid = threadIdx.x;
    int wid = tid >> 5, lane = tid & 31;

    float4 v = *(const float4*)(g_att + (size_t)row * Dd + tid * 4);

    float s = v.x + v.y + v.z + v.w;
#pragma unroll
    for (int o = 16; o; o >>= 1) s += __shfl_xor_sync(0xffffffffu, s, o);
    if (lane == 0) sb2[wid] = s;
    __syncthreads();
    if (tid < 8) {
        float t = sb2[tid];
#pragma unroll
        for (int o = 4; o; o >>= 1) t += __shfl_xor_sync(0xFFu, t, o);
        if (tid == 0) sb2[0] = t;
    }
    __syncthreads();
    float mean = sb2[0] * (1.0f / Dd);
    __syncthreads();

    float dx = v.x - mean, dy = v.y - mean, dz = v.z - mean, dw = v.w - mean;
    float vv = dx * dx + dy * dy + dz * dz + dw * dw;
#pragma unroll
    for (int o = 16; o; o >>= 1) vv += __shfl_xor_sync(0xffffffffu, vv, o);
    if (lane == 0) sb2[wid] = vv;
    __syncthreads();
    if (tid < 8) {
        float t = sb2[tid];
#pragma unroll
        for (int o = 4; o; o >>= 1) t += __shfl_xor_sync(0xFFu, t, o);
        if (tid == 0) sb2[0] = t;
    }
    __syncthreads();
    float inv = rsqrtf(sb2[0] * (1.0f / Dd) + EPS_);

    float4 w4 = *(const float4*)(w  + tid * 4);
    float4 b4 = *(const float4*)(bi + tid * 4);
    float rx = dx * inv * w4.x + b4.x;
    float ry = dy * inv * w4.y + b4.y;
    float rz = dz * inv * w4.z + b4.z;
    float rw = dw * inv * w4.w + b4.w;

    __nv_bfloat162 h01 = __floats2bfloat162_rn(rx, ry);
    __nv_bfloat162 h23 = __floats2bfloat162_rn(rz, rw);
    float2 f01 = __bfloat1622float2(h01), f23 = __bfloat1622float2(h23);
    __nv_bfloat162 l01 = __floats2bfloat162_rn(rx - f01.x, ry - f01.y);
    __nv_bfloat162 l23 = __floats2bfloat162_rn(rz - f23.x, rw - f23.y);
    __nv_bfloat162* ph = (__nv_bfloat162*)(g_xh + (size_t)row * Dd + tid * 4);
    __nv_bfloat162* pl = (__nv_bfloat162*)(g_xl + (size_t)row * Dd + tid * 4);
    ph[0] = h01; ph[1] = h23;
    pl[0] = l01; pl[1] = l23;
}

// ---------------------------------------------------------------------------
// Kernel 4: out = xln @ proj_w^T via bf16 3-term MMAs (R12 synchronous form).
// Block = 128(m) x 64(n), BK=64.
// ---------------------------------------------------------------------------
__global__ __launch_bounds__(256, 2)
void proj_tc_kernel(float* __restrict__ out)
{
    extern __shared__ __nv_bfloat16 sbm[];
    __nv_bfloat16* sXh = sbm;                    // 128*72
    __nv_bfloat16* sXl = sXh + 128 * BSTR;
    __nv_bfloat16* sWh = sXl + 128 * BSTR;      // 64*72
    __nv_bfloat16* sWl = sWh + 64 * BSTR;

    const int m0 = blockIdx.y * 128;
    const int n0 = blockIdx.x * 64;
    const int tid = threadIdx.x, wid = tid >> 5, lane = tid & 31;
    const int gr = lane >> 2, tc = lane & 3;
    const int qr = wid * 16;

    const uint32_t* uXh = (const uint32_t*)sXh;
    const uint32_t* uXl = (const uint32_t*)sXl;
    const uint32_t* uWh = (const uint32_t*)sWh;
    const uint32_t* uWl = (const uint32_t*)sWl;

    float oa[8][4];
#pragma unroll
    for (int j = 0; j < 8; ++j) { oa[j][0] = oa[j][1] = oa[j][2] = oa[j][3] = 0.0f; }

    const int r0u = (qr + gr) * USTR, r1u = (qr + gr + 8) * USTR;

    for (int kt = 0; kt < Dd; kt += 64) {
        __syncthreads();
#pragma unroll
        for (int i = 0; i < 4; ++i) {
            int idx = i * 256 + tid;
            int row = idx >> 3, c8 = (idx & 7) * 8;
            *(uint4*)&sXh[row * BSTR + c8] = *(const uint4*)(g_xh + (size_t)(m0 + row) * Dd + kt + c8);
            *(uint4*)&sXl[row * BSTR + c8] = *(const uint4*)(g_xl + (size_t)(m0 + row) * Dd + kt + c8);
        }
#pragma unroll
        for (int i = 0; i < 2; ++i) {
            int idx = i * 256 + tid;
            int row = idx >> 3, c8 = (idx & 7) * 8;
            *(uint4*)&sWh[row * BSTR + c8] = *(const uint4*)(g_wh + (size_t)(n0 + row) * Dd + kt + c8);
            *(uint4*)&sWl[row * BSTR + c8] = *(const uint4*)(g_wl + (size_t)(n0 + row) * Dd + kt + c8);
        }
        __syncthreads();

#pragma unroll
        for (int c = 0; c < 4; ++c) {
            uint32_t ah0 = uXh[r0u + c * 8 + tc],     ah1 = uXh[r1u + c * 8 + tc];
            uint32_t ah2 = uXh[r0u + c * 8 + 4 + tc], ah3 = uXh[r1u + c * 8 + 4 + tc];
            uint32_t al0 = uXl[r0u + c * 8 + tc],     al1 = uXl[r1u + c * 8 + tc];
            uint32_t al2 = uXl[r0u + c * 8 + 4 + tc], al3 = uXl[r1u + c * 8 + 4 + tc];
#pragma unroll
            for (int j = 0; j < 8; ++j) {
                int bi = (j * 8 + gr) * USTR + c * 8 + tc;
                uint32_t bh0 = uWh[bi], bh1 = uWh[bi + 4];
                uint32_t bl0 = uWl[bi], bl1 = uWl[bi + 4];
                MMA3(oa[j], ah0,ah1,ah2,ah3, al0,al1,al2,al3, bh0,bh1, bl0,bl1);
            }
        }
    }

    size_t r0 = (size_t)(m0 + qr + gr) * Dd + n0;
    size_t r1 = r0 + (size_t)8 * Dd;
#pragma unroll
    for (int j = 0; j < 8; ++j) {
        *(float2*)(out + r0 + j * 8 + 2 * tc) = make_float2(oa[j][0], oa[j][1]);
        *(float2*)(out + r1 + j * 8 + 2 * tc) = make_float2(oa[j][2], oa[j][3]);
    }
}

// ---------------------------------------------------------------------------
// Launch
// Inputs: 0 x_q, 1 x_k, 2 x_v, 3 qn_w, 4 qn_b, 5 kn_w, 6 kn_b, 7 n_w, 8 n_b, 9 proj_w
// ---------------------------------------------------------------------------
extern "C" void kernel_launch(void* const* d_in, const int* in_sizes, int n_in,
                              void* d_out, int out_size)
{
    const float* xq  = (const float*)d_in[0];
    const float* xk  = (const float*)d_in[1];
    const float* xv  = (const float*)d_in[2];
    const float* qnw = (const float*)d_in[3];
    const float* qnb = (const float*)d_in[4];
    const float* knw = (const float*)d_in[5];
    const float* knb = (const float*)d_in[6];
    const float* nw  = (const float*)d_in[7];
    const float* nb  = (const float*)d_in[8];
    const float* pw  = (const float*)d_in[9];
    float* out = (float*)d_out;

    const int ATTN_SMEM = (2 * 128 * BSTR + 2 * 4 * 64 * BSTR) * 2;   // 110592 B
    const int PROJ_SMEM = (2 * 128 * BSTR + 2 * 64 * BSTR) * 2;       // 55296 B
    cudaFuncSetAttribute(attn_tc_kernel, cudaFuncAttributeMaxDynamicSharedMemorySize, ATTN_SMEM);
    cudaFuncSetAttribute(proj_tc_kernel, cudaFuncAttributeMaxDynamicSharedMemorySize, PROJ_SMEM);

    // 1) prep: K layernorm+split, V transpose+split, W split
    kln_kernel<<<(Bb * Nn) / 8, 256>>>(xk, knw, knb);
    dim3 vgrid(Nn / 64, Bb);
    vprep_kernel<<<vgrid, 256>>>(xv);
    wprep_kernel<<<(Dd * Dd / 4) / 256, 256>>>(pw);

    // 2) bf16 tensor-core flash attention : (S/128, H, B)
    dim3 agrid(Ss / 128, Hh, Bb);
    attn_tc_kernel<<<agrid, 256, ATTN_SMEM>>>(xq, qnw, qnb);

    // 3) layernorm over D (emits bf16 hi/lo)
    lnd_kernel<<<Bb * Ss, 256>>>(nw, nb);

    // 4) projection GEMM : (N/64, M/128)
    dim3 pgrid(Dd / 64, (Bb * Ss) / 128);
    proj_tc_kernel<<<pgrid, 256, PROJ_SMEM>>>(out);
}